// round 13
// baseline (speedup 1.0000x reference)
#include <cuda_runtime.h>
#include <cuda_bf16.h>
#include <cstdint>

#define NC     2048
#define D      256
#define NROWS  32768
#define BM     128          // rows per CTA in approx kernel
#define CHUNK  64           // centroids per chunk
#define NCHUNK (NC / CHUNK) // 32
#define RING   3
#define SLOTSZ (CHUNK * 528)   // 33792 B per ring slot

// Output layout (float32):
#define OFF_Q    0
#define OFF_L    8388608
#define OFF_NN   16777216
#define OFF_CB   16809984
#define OFF_CNT  17334272

// SMEM map (bytes): ring (X staged here transiently) then cn.
#define SM_RING  0
#define SM_CN    (RING * SLOTSZ)          // 101376
#define SM_TOTAL (SM_CN + NC * 4)         // 109568 -> 2 CTAs/SM

// scratch (allocation-free)
__device__ float          g_cnorm[NC];
__device__ float          g_srow[NROWS];
__device__ __nv_bfloat16  g_cb[NC * D];
__device__ unsigned int   g_cand[NROWS * 4];
__device__ int            g_hist[NC];
__device__ int            g_done;          // zero-init; reset by last rescore CTA

__device__ __forceinline__ uint32_t smem_u32(const void* p) {
    uint32_t a;
    asm("{ .reg .u64 t; cvta.to.shared.u64 t, %1; cvt.u32.u64 %0, t; }" : "=r"(a) : "l"(p));
    return a;
}

__device__ __forceinline__ void insert4(unsigned long long* t, unsigned long long u) {
    if (u < t[3]) {
        if (u < t[2]) {
            t[3] = t[2];
            if (u < t[1]) {
                t[2] = t[1];
                if (u < t[0]) { t[1] = t[0]; t[0] = u; } else t[1] = u;
            } else t[2] = u;
        } else t[3] = u;
    }
}

// sequential-order ||row||^2 with deep load batching (MLP=16) — the fadd
// chain order q=0..255 is unchanged, only load scheduling is widened.
__device__ __forceinline__ float row_norm_seq(const float4* row) {
    float s = 0.0f;
#pragma unroll
    for (int phase = 0; phase < 4; phase++) {
        float4 v[16];
#pragma unroll
        for (int i = 0; i < 16; i++) v[i] = row[phase * 16 + i];
#pragma unroll
        for (int i = 0; i < 16; i++) {
            s = __fadd_rn(s, __fmul_rn(v[i].x, v[i].x));
            s = __fadd_rn(s, __fmul_rn(v[i].y, v[i].y));
            s = __fadd_rn(s, __fmul_rn(v[i].z, v[i].z));
            s = __fadd_rn(s, __fmul_rn(v[i].w, v[i].w));
        }
    }
    return s;
}

// ---------------------------------------------------------------------------
// K0: merged init. blocks [0,128): per-row ||x||^2 sequential fp32 (batched).
// blocks [128,384): cnorm + codebook copy + bf16 codebook + hist init.
// ---------------------------------------------------------------------------
__global__ void __launch_bounds__(256) init_kernel(const float* __restrict__ x,
                                                   const float* __restrict__ cb,
                                                   float* __restrict__ outcb) {
    int b = blockIdx.x;
    if (b < 128) {
        int r = b * 256 + threadIdx.x;
        g_srow[r] = row_norm_seq((const float4*)(x + (size_t)r * D));
        return;
    }
    int gid = (b - 128) * 256 + threadIdx.x;   // 0..65535
    if (gid < NC) g_hist[gid] = 0;

    int wid  = gid >> 5;
    int lane = gid & 31;
    const float* row  = cb    + (size_t)wid * D;
    float*       orow = outcb + (size_t)wid * D;
#pragma unroll
    for (int j = 0; j < 8; j++) orow[lane + 32 * j] = row[lane + 32 * j];

    if (gid < NC)
        g_cnorm[gid] = row_norm_seq((const float4*)(cb + (size_t)gid * D));

    // bf16 codebook: 8 floats/thread
    {
        const float4* src = (const float4*)cb;
        float4 v0 = src[gid * 2], v1 = src[gid * 2 + 1];
        __nv_bfloat16 bb[8];
        bb[0] = __float2bfloat16(v0.x); bb[1] = __float2bfloat16(v0.y);
        bb[2] = __float2bfloat16(v0.z); bb[3] = __float2bfloat16(v0.w);
        bb[4] = __float2bfloat16(v1.x); bb[5] = __float2bfloat16(v1.y);
        bb[6] = __float2bfloat16(v1.z); bb[7] = __float2bfloat16(v1.w);
        ((uint4*)g_cb)[gid] = *(uint4*)bb;
    }
}

// cp.async one 64-centroid bf16 chunk into a ring slot (row stride 528B)
__device__ __forceinline__ void stage_c(uint32_t dst, int cbase, int tid) {
    const char* src = (const char*)(g_cb + (size_t)cbase * D);
#pragma unroll
    for (int i = 0; i < 8; i++) {
        int idx = tid + i * 256;              // 0..2047
        int r = idx >> 5, kp = (idx & 31) * 16;
        uint32_t d = dst + (uint32_t)(r * 528 + kp);
        const char* s = src + r * 512 + kp;
        asm volatile("cp.async.ca.shared.global [%0], [%1], 16;" :: "r"(d), "l"(s));
    }
}

// ---------------------------------------------------------------------------
// K2: HMMA bf16 approx GEMM + fused per-row top-4. 256 thr, 2 CTAs/SM.
// CTA: 128 rows x 2048 centroids. Warp w owns rows [w*16, w*16+16).
// Positive-offset keys: cn_sm = cn + 64 so score > 0 and raw float bits sort.
// ---------------------------------------------------------------------------
__global__ void __launch_bounds__(256, 2) approx_kernel(const float* __restrict__ x) {
    extern __shared__ char sm[];
    float* cn_sm = (float*)(sm + SM_CN);
    const int tid  = threadIdx.x;
    const int lane = tid & 31;
    const int w    = tid >> 5;
    const int rowBase = blockIdx.x * BM;
    const uint32_t smb = smem_u32(sm);

    for (int i = tid; i < NC; i += 256) cn_sm[i] = g_cnorm[i] + 64.0f;

    // stage X (fp32 -> bf16) into ring region transiently (128 * 528 B)
#pragma unroll
    for (int i = 0; i < 16; i++) {
        int idx = tid + i * 256;
        int r = idx >> 5, kp = (idx & 31) * 8;
        const float4* src = (const float4*)(x + (size_t)(rowBase + r) * D + kp);
        float4 v0 = src[0], v1 = src[1];
        __nv_bfloat16 bb[8];
        bb[0] = __float2bfloat16(v0.x); bb[1] = __float2bfloat16(v0.y);
        bb[2] = __float2bfloat16(v0.z); bb[3] = __float2bfloat16(v0.w);
        bb[4] = __float2bfloat16(v1.x); bb[5] = __float2bfloat16(v1.y);
        bb[6] = __float2bfloat16(v1.z); bb[7] = __float2bfloat16(v1.w);
        *(uint4*)(sm + r * 528 + kp * 2) = *(uint4*)bb;
    }
    __syncthreads();

    // A fragments held in regs: 16 k-blocks (m16k16 each)
    uint32_t a[16][4];
#pragma unroll
    for (int kb = 0; kb < 16; kb++) {
        uint32_t addr = smb + (uint32_t)((w * 16 + (lane & 15)) * 528
                                         + (kb * 16 + (lane >> 4) * 8) * 2);
        asm volatile("ldmatrix.sync.aligned.m8n8.x4.shared.b16 {%0,%1,%2,%3}, [%4];"
                     : "=r"(a[kb][0]), "=r"(a[kb][1]), "=r"(a[kb][2]), "=r"(a[kb][3])
                     : "r"(addr));
    }
    __syncthreads();   // X region now dead; becomes the C ring

    // prologue: stage chunks 0 and 1 into slots 0 and 1
    stage_c(smb + SM_RING + 0 * SLOTSZ, 0 * CHUNK, tid);
    asm volatile("cp.async.commit_group;" ::: "memory");
    stage_c(smb + SM_RING + 1 * SLOTSZ, 1 * CHUNK, tid);
    asm volatile("cp.async.commit_group;" ::: "memory");

    unsigned long long top[2][4];
#pragma unroll
    for (int h = 0; h < 2; h++)
#pragma unroll
        for (int j = 0; j < 4; j++) top[h][j] = 0xFFFFFFFFFFFFFFFFULL;

    const uint32_t bRowOff = (uint32_t)(((lane & 7) + (lane >> 4) * 8) * 528
                                        + ((lane >> 3) & 1) * 16);

    int slot = 0;
    for (int ch = 0; ch < NCHUNK; ch++) {
        asm volatile("cp.async.wait_group 1;" ::: "memory");
        __syncthreads();   // slot `slot` (chunk ch) visible to all warps

        const uint32_t cbB = smb + (uint32_t)(SM_RING + slot * SLOTSZ) + bRowOff;

#pragma unroll
        for (int half = 0; half < 2; half++) {
            float acc[4][4];
#pragma unroll
            for (int nt = 0; nt < 4; nt++)
#pragma unroll
                for (int e = 0; e < 4; e++) acc[nt][e] = 0.0f;

            // flattened steps s = kb*2 + np; 2-slot B-frag ring, prefetch +2
            uint32_t bb[2][4];
#pragma unroll
            for (int p = 0; p < 2; p++) {
                uint32_t addr = cbB + (uint32_t)((half * 32 + p * 16) * 528);
                asm volatile("ldmatrix.sync.aligned.m8n8.x4.shared.b16 {%0,%1,%2,%3}, [%4];"
                             : "=r"(bb[p][0]), "=r"(bb[p][1]), "=r"(bb[p][2]), "=r"(bb[p][3])
                             : "r"(addr));
            }
#pragma unroll
            for (int s = 0; s < 32; s++) {
                const int kb = s >> 1, np = s & 1;
                asm volatile("mma.sync.aligned.m16n8k16.row.col.f32.bf16.bf16.f32 "
                             "{%0,%1,%2,%3}, {%4,%5,%6,%7}, {%8,%9}, {%0,%1,%2,%3};"
                             : "+f"(acc[np*2][0]), "+f"(acc[np*2][1]),
                               "+f"(acc[np*2][2]), "+f"(acc[np*2][3])
                             : "r"(a[kb][0]), "r"(a[kb][1]), "r"(a[kb][2]), "r"(a[kb][3]),
                               "r"(bb[s & 1][0]), "r"(bb[s & 1][1]));
                asm volatile("mma.sync.aligned.m16n8k16.row.col.f32.bf16.bf16.f32 "
                             "{%0,%1,%2,%3}, {%4,%5,%6,%7}, {%8,%9}, {%0,%1,%2,%3};"
                             : "+f"(acc[np*2+1][0]), "+f"(acc[np*2+1][1]),
                               "+f"(acc[np*2+1][2]), "+f"(acc[np*2+1][3])
                             : "r"(a[kb][0]), "r"(a[kb][1]), "r"(a[kb][2]), "r"(a[kb][3]),
                               "r"(bb[s & 1][2]), "r"(bb[s & 1][3]));
                if (s + 2 < 32) {
                    const int s2 = s + 2;
                    uint32_t addr = cbB + (uint32_t)((half * 32 + (s2 & 1) * 16) * 528
                                                     + ((s2 >> 1) * 16) * 2);
                    asm volatile("ldmatrix.sync.aligned.m8n8.x4.shared.b16 {%0,%1,%2,%3}, [%4];"
                                 : "=r"(bb[s & 1][0]), "=r"(bb[s & 1][1]),
                                   "=r"(bb[s & 1][2]), "=r"(bb[s & 1][3])
                                 : "r"(addr));
                }
            }

            // epilogue: score+64 > 0 -> raw float bits are the sort key
            int kbase = ch * CHUNK + half * 32 + (lane & 3) * 2;
#pragma unroll
            for (int nt = 0; nt < 4; nt++) {
#pragma unroll
                for (int e = 0; e < 4; e++) {
                    int k = kbase + nt * 8 + (e & 1);
                    float sc = __fmaf_rn(-2.0f, acc[nt][e], cn_sm[k]);
                    unsigned long long u;
                    asm("mov.b64 %0, {%1, %2};"
                        : "=l"(u) : "r"((uint32_t)k), "r"(__float_as_uint(sc)));
                    insert4(top[e >> 1], u);
                }
            }
        }

        // stage chunk ch+2 into the slot consumed at iter ch-1 (safe: sync above)
        if (ch + 2 < NCHUNK) {
            int ns = slot + 2; if (ns >= RING) ns -= RING;
            stage_c(smb + (uint32_t)(SM_RING + ns * SLOTSZ), (ch + 2) * CHUNK, tid);
        }
        asm volatile("cp.async.commit_group;" ::: "memory");  // one group per iter
        slot = (slot + 1 == RING) ? 0 : slot + 1;
    }

    // merge top-4 across the 4 lanes sharing each row, write candidates
#pragma unroll
    for (int h = 0; h < 2; h++) {
        unsigned long long v0 = top[h][0], v1 = top[h][1], v2 = top[h][2], v3 = top[h][3];
#pragma unroll
        for (int m = 1; m <= 2; m <<= 1) {
            unsigned long long o0 = __shfl_xor_sync(0xFFFFFFFFu, v0, m);
            unsigned long long o1 = __shfl_xor_sync(0xFFFFFFFFu, v1, m);
            unsigned long long o2 = __shfl_xor_sync(0xFFFFFFFFu, v2, m);
            unsigned long long o3 = __shfl_xor_sync(0xFFFFFFFFu, v3, m);
            unsigned long long s0 = v0 < o3 ? v0 : o3;
            unsigned long long s1 = v1 < o2 ? v1 : o2;
            unsigned long long s2 = v2 < o1 ? v2 : o1;
            unsigned long long s3 = v3 < o0 ? v3 : o0;
            unsigned long long a0 = s0 < s2 ? s0 : s2, a2 = s0 < s2 ? s2 : s0;
            unsigned long long a1 = s1 < s3 ? s1 : s3, a3 = s1 < s3 ? s3 : s1;
            v0 = a0 < a1 ? a0 : a1; v1 = a0 < a1 ? a1 : a0;
            v2 = a2 < a3 ? a2 : a3; v3 = a2 < a3 ? a3 : a2;
        }
        if ((lane & 3) == 0) {
            int row = rowBase + w * 16 + (lane >> 2) + h * 8;
            uint4 st;
            st.x = (uint32_t)v0; st.y = (uint32_t)v1;
            st.z = (uint32_t)v2; st.w = (uint32_t)v3;
            *(uint4*)&g_cand[row * 4] = st;
        }
    }
}

// ---------------------------------------------------------------------------
// K3: fused exact rescore + gather + loss + hist + (last CTA) EMA counts.
// warp = row; lane = (cand c = lane>>3, seg s = lane&7); element float4 q*8+s.
// ---------------------------------------------------------------------------
__global__ void __launch_bounds__(256, 3) rescore_gather_kernel(const float* __restrict__ x,
                                                                const float* __restrict__ cb,
                                                                const float* __restrict__ cc,
                                                                float* __restrict__ outq,
                                                                float* __restrict__ outl,
                                                                float* __restrict__ outnn,
                                                                float* __restrict__ outcnt) {
    int row  = (blockIdx.x * blockDim.x + threadIdx.x) >> 5;
    int lane = threadIdx.x & 31;
    int c = lane >> 3, s = lane & 7;

    unsigned int cand = g_cand[row * 4 + c];
    const float4* c4 = (const float4*)(cb + (size_t)cand * D);
    const float4* x4 = (const float4*)(x + (size_t)row * D);

    float d = 0.0f;
#pragma unroll
    for (int q = 0; q < 8; q++) {
        float4 cq = c4[q * 8 + s];
        float4 xq = x4[q * 8 + s];
        d = __fmaf_rn(xq.x, cq.x, d);
        d = __fmaf_rn(xq.y, cq.y, d);
        d = __fmaf_rn(xq.z, cq.z, d);
        d = __fmaf_rn(xq.w, cq.w, d);
    }
    d = __fadd_rn(d, __shfl_xor_sync(0xFFFFFFFFu, d, 1));
    d = __fadd_rn(d, __shfl_xor_sync(0xFFFFFFFFu, d, 2));
    d = __fadd_rn(d, __shfl_xor_sync(0xFFFFFFFFu, d, 4));

    float sc = __fadd_rn(__fmaf_rn(-2.0f, d, g_srow[row]), g_cnorm[cand]);
    uint32_t bb  = __float_as_uint(sc);
    uint32_t key = (bb & 0x80000000u) ? ~bb : (bb | 0x80000000u);
    unsigned long long best = ((unsigned long long)key << 32) | cand;

    unsigned long long o;
    o = __shfl_xor_sync(0xFFFFFFFFu, best, 8);  best = o < best ? o : best;
    o = __shfl_xor_sync(0xFFFFFFFFu, best, 16); best = o < best ? o : best;
    unsigned int wc = (unsigned int)best;

    if (lane == 0) {
        atomicAdd(&g_hist[wc], 1);
        outnn[row] = (float)wc;
    }

    if (cand == wc) {   // exactly one group (candidates are distinct)
        float4* qr = (float4*)(outq + (size_t)row * D);
        float4* lr = (float4*)(outl + (size_t)row * D);
#pragma unroll
        for (int q = 0; q < 8; q++) {
            float4 cq = c4[q * 8 + s];   // L1 hit
            float4 xq = x4[q * 8 + s];   // L1 hit
            qr[q * 8 + s] = cq;
            float4 L;
            L.x = 1.25f * (cq.x - xq.x) * (cq.x - xq.x);
            L.y = 1.25f * (cq.y - xq.y) * (cq.y - xq.y);
            L.z = 1.25f * (cq.z - xq.z) * (cq.z - xq.z);
            L.w = 1.25f * (cq.w - xq.w) * (cq.w - xq.w);
            lr[q * 8 + s] = L;
        }
    }

    // last-CTA-done: EMA counts (removes a separate launch)
    __shared__ int is_last;
    __syncthreads();
    if (threadIdx.x == 0) {
        __threadfence();
        is_last = (atomicAdd(&g_done, 1) == (int)gridDim.x - 1);
    }
    __syncthreads();
    if (is_last) {
#pragma unroll
        for (int k0 = 0; k0 < NC / 256; k0++) {
            int k = k0 * 256 + threadIdx.x;
            outcnt[k] = 0.99f * cc[k] + 0.01f * (float)g_hist[k];
        }
        __syncthreads();
        if (threadIdx.x == 0) g_done = 0;   // reset for next graph replay
    }
}

// ---------------------------------------------------------------------------
extern "C" void kernel_launch(void* const* d_in, const int* in_sizes, int n_in,
                              void* d_out, int out_size) {
    const float* x  = (const float*)d_in[0];
    const float* cb = (const float*)d_in[1];
    const float* cc = (const float*)d_in[2];
    float* out = (float*)d_out;

    cudaFuncSetAttribute(approx_kernel,
                         cudaFuncAttributeMaxDynamicSharedMemorySize, SM_TOTAL);

    init_kernel<<<384, 256>>>(x, cb, out + OFF_CB);
    approx_kernel<<<NROWS / BM, 256, SM_TOTAL>>>(x);
    rescore_gather_kernel<<<NROWS * 32 / 256, 256>>>(x, cb, cc,
                                                     out + OFF_Q, out + OFF_L,
                                                     out + OFF_NN, out + OFF_CNT);
}

// round 14
// speedup vs baseline: 1.0081x; 1.0081x over previous
#include <cuda_runtime.h>
#include <cuda_bf16.h>
#include <cstdint>

#define NC     2048
#define D      256
#define NROWS  32768
#define BM     128          // rows per CTA in approx kernel
#define CHUNK  64           // centroids per chunk
#define NCHUNK (NC / CHUNK) // 32
#define RING   3
#define SLOTSZ (CHUNK * 528)   // 33792 B per ring slot

// Output layout (float32):
#define OFF_Q    0
#define OFF_L    8388608
#define OFF_NN   16777216
#define OFF_CB   16809984
#define OFF_CNT  17334272

// SMEM map (bytes): ring (X staged here transiently) then cn.
#define SM_RING  0
#define SM_CN    (RING * SLOTSZ)          // 101376
#define SM_TOTAL (SM_CN + NC * 4)         // 109568 -> 2 CTAs/SM

// scratch (allocation-free)
__device__ float          g_cnorm[NC];
__device__ float          g_srow[NROWS];
__device__ __nv_bfloat16  g_cb[NC * D];
__device__ unsigned int   g_cand[NROWS * 4];
__device__ int            g_hist[NC];
__device__ int            g_done;          // zero-init; reset by last rescore CTA

__device__ __forceinline__ uint32_t smem_u32(const void* p) {
    uint32_t a;
    asm("{ .reg .u64 t; cvta.to.shared.u64 t, %1; cvt.u32.u64 %0, t; }" : "=r"(a) : "l"(p));
    return a;
}

__device__ __forceinline__ void insert4(unsigned long long* t, unsigned long long u) {
    if (u < t[3]) {
        if (u < t[2]) {
            t[3] = t[2];
            if (u < t[1]) {
                t[2] = t[1];
                if (u < t[0]) { t[1] = t[0]; t[0] = u; } else t[1] = u;
            } else t[2] = u;
        } else t[3] = u;
    }
}

// sequential-order ||row||^2. Loads forced front-batched (MLP=16) with
// volatile asm so ptxas cannot sink them into the fadd chain; the fp add
// order q=0..255 is UNCHANGED (bit-identical result vs prior rounds).
__device__ __forceinline__ float row_norm_seq(const float* row) {
    float s = 0.0f;
#pragma unroll
    for (int ph = 0; ph < 4; ph++) {
        float v[64];
#pragma unroll
        for (int i = 0; i < 16; i++) {
            asm volatile("ld.global.nc.v4.f32 {%0,%1,%2,%3}, [%4];"
                         : "=f"(v[i * 4 + 0]), "=f"(v[i * 4 + 1]),
                           "=f"(v[i * 4 + 2]), "=f"(v[i * 4 + 3])
                         : "l"(row + ph * 64 + i * 4));
        }
#pragma unroll
        for (int i = 0; i < 64; i++)
            s = __fadd_rn(s, __fmul_rn(v[i], v[i]));
    }
    return s;
}

// ---------------------------------------------------------------------------
// K0: merged init. blocks [0,128): per-row ||x||^2 sequential fp32 (forced MLP).
// blocks [128,384): cnorm + codebook copy + bf16 codebook + hist init.
// ---------------------------------------------------------------------------
__global__ void __launch_bounds__(256) init_kernel(const float* __restrict__ x,
                                                   const float* __restrict__ cb,
                                                   float* __restrict__ outcb) {
    int b = blockIdx.x;
    if (b < 128) {
        int r = b * 256 + threadIdx.x;
        g_srow[r] = row_norm_seq(x + (size_t)r * D);
        return;
    }
    int gid = (b - 128) * 256 + threadIdx.x;   // 0..65535
    if (gid < NC) g_hist[gid] = 0;

    int wid  = gid >> 5;
    int lane = gid & 31;
    const float* row  = cb    + (size_t)wid * D;
    float*       orow = outcb + (size_t)wid * D;
#pragma unroll
    for (int j = 0; j < 8; j++) orow[lane + 32 * j] = row[lane + 32 * j];

    if (gid < NC)
        g_cnorm[gid] = row_norm_seq(cb + (size_t)gid * D);

    // bf16 codebook: 8 floats/thread
    {
        const float4* src = (const float4*)cb;
        float4 v0 = src[gid * 2], v1 = src[gid * 2 + 1];
        __nv_bfloat16 bb[8];
        bb[0] = __float2bfloat16(v0.x); bb[1] = __float2bfloat16(v0.y);
        bb[2] = __float2bfloat16(v0.z); bb[3] = __float2bfloat16(v0.w);
        bb[4] = __float2bfloat16(v1.x); bb[5] = __float2bfloat16(v1.y);
        bb[6] = __float2bfloat16(v1.z); bb[7] = __float2bfloat16(v1.w);
        ((uint4*)g_cb)[gid] = *(uint4*)bb;
    }
}

// cp.async one 64-centroid bf16 chunk into a ring slot (row stride 528B)
__device__ __forceinline__ void stage_c(uint32_t dst, int cbase, int tid) {
    const char* src = (const char*)(g_cb + (size_t)cbase * D);
#pragma unroll
    for (int i = 0; i < 8; i++) {
        int idx = tid + i * 256;              // 0..2047
        int r = idx >> 5, kp = (idx & 31) * 16;
        uint32_t d = dst + (uint32_t)(r * 528 + kp);
        const char* s = src + r * 512 + kp;
        asm volatile("cp.async.ca.shared.global [%0], [%1], 16;" :: "r"(d), "l"(s));
    }
}

// ---------------------------------------------------------------------------
// K2: HMMA bf16 approx GEMM + fused per-row top-4. 256 thr, 2 CTAs/SM.
// CTA: 128 rows x 2048 centroids. Warp w owns rows [w*16, w*16+16).
// Positive-offset keys: cn_sm = cn + 64 so score > 0 and raw float bits sort.
// ---------------------------------------------------------------------------
__global__ void __launch_bounds__(256, 2) approx_kernel(const float* __restrict__ x) {
    extern __shared__ char sm[];
    float* cn_sm = (float*)(sm + SM_CN);
    const int tid  = threadIdx.x;
    const int lane = tid & 31;
    const int w    = tid >> 5;
    const int rowBase = blockIdx.x * BM;
    const uint32_t smb = smem_u32(sm);

    for (int i = tid; i < NC; i += 256) cn_sm[i] = g_cnorm[i] + 64.0f;

    // stage X (fp32 -> bf16) into ring region transiently (128 * 528 B)
#pragma unroll
    for (int i = 0; i < 16; i++) {
        int idx = tid + i * 256;
        int r = idx >> 5, kp = (idx & 31) * 8;
        const float4* src = (const float4*)(x + (size_t)(rowBase + r) * D + kp);
        float4 v0 = src[0], v1 = src[1];
        __nv_bfloat16 bb[8];
        bb[0] = __float2bfloat16(v0.x); bb[1] = __float2bfloat16(v0.y);
        bb[2] = __float2bfloat16(v0.z); bb[3] = __float2bfloat16(v0.w);
        bb[4] = __float2bfloat16(v1.x); bb[5] = __float2bfloat16(v1.y);
        bb[6] = __float2bfloat16(v1.z); bb[7] = __float2bfloat16(v1.w);
        *(uint4*)(sm + r * 528 + kp * 2) = *(uint4*)bb;
    }
    __syncthreads();

    // A fragments held in regs: 16 k-blocks (m16k16 each)
    uint32_t a[16][4];
#pragma unroll
    for (int kb = 0; kb < 16; kb++) {
        uint32_t addr = smb + (uint32_t)((w * 16 + (lane & 15)) * 528
                                         + (kb * 16 + (lane >> 4) * 8) * 2);
        asm volatile("ldmatrix.sync.aligned.m8n8.x4.shared.b16 {%0,%1,%2,%3}, [%4];"
                     : "=r"(a[kb][0]), "=r"(a[kb][1]), "=r"(a[kb][2]), "=r"(a[kb][3])
                     : "r"(addr));
    }
    __syncthreads();   // X region now dead; becomes the C ring

    // prologue: stage chunks 0 and 1 into slots 0 and 1
    stage_c(smb + SM_RING + 0 * SLOTSZ, 0 * CHUNK, tid);
    asm volatile("cp.async.commit_group;" ::: "memory");
    stage_c(smb + SM_RING + 1 * SLOTSZ, 1 * CHUNK, tid);
    asm volatile("cp.async.commit_group;" ::: "memory");

    unsigned long long top[2][4];
#pragma unroll
    for (int h = 0; h < 2; h++)
#pragma unroll
        for (int j = 0; j < 4; j++) top[h][j] = 0xFFFFFFFFFFFFFFFFULL;

    const uint32_t bRowOff = (uint32_t)(((lane & 7) + (lane >> 4) * 8) * 528
                                        + ((lane >> 3) & 1) * 16);

    int slot = 0;
    for (int ch = 0; ch < NCHUNK; ch++) {
        asm volatile("cp.async.wait_group 1;" ::: "memory");
        __syncthreads();   // slot `slot` (chunk ch) visible to all warps

        const uint32_t cbB = smb + (uint32_t)(SM_RING + slot * SLOTSZ) + bRowOff;

#pragma unroll
        for (int half = 0; half < 2; half++) {
            float acc[4][4];
#pragma unroll
            for (int nt = 0; nt < 4; nt++)
#pragma unroll
                for (int e = 0; e < 4; e++) acc[nt][e] = 0.0f;

            // flattened steps s = kb*2 + np; 2-slot B-frag ring, prefetch +2
            uint32_t bb[2][4];
#pragma unroll
            for (int p = 0; p < 2; p++) {
                uint32_t addr = cbB + (uint32_t)((half * 32 + p * 16) * 528);
                asm volatile("ldmatrix.sync.aligned.m8n8.x4.shared.b16 {%0,%1,%2,%3}, [%4];"
                             : "=r"(bb[p][0]), "=r"(bb[p][1]), "=r"(bb[p][2]), "=r"(bb[p][3])
                             : "r"(addr));
            }
#pragma unroll
            for (int s = 0; s < 32; s++) {
                const int kb = s >> 1, np = s & 1;
                asm volatile("mma.sync.aligned.m16n8k16.row.col.f32.bf16.bf16.f32 "
                             "{%0,%1,%2,%3}, {%4,%5,%6,%7}, {%8,%9}, {%0,%1,%2,%3};"
                             : "+f"(acc[np*2][0]), "+f"(acc[np*2][1]),
                               "+f"(acc[np*2][2]), "+f"(acc[np*2][3])
                             : "r"(a[kb][0]), "r"(a[kb][1]), "r"(a[kb][2]), "r"(a[kb][3]),
                               "r"(bb[s & 1][0]), "r"(bb[s & 1][1]));
                asm volatile("mma.sync.aligned.m16n8k16.row.col.f32.bf16.bf16.f32 "
                             "{%0,%1,%2,%3}, {%4,%5,%6,%7}, {%8,%9}, {%0,%1,%2,%3};"
                             : "+f"(acc[np*2+1][0]), "+f"(acc[np*2+1][1]),
                               "+f"(acc[np*2+1][2]), "+f"(acc[np*2+1][3])
                             : "r"(a[kb][0]), "r"(a[kb][1]), "r"(a[kb][2]), "r"(a[kb][3]),
                               "r"(bb[s & 1][2]), "r"(bb[s & 1][3]));
                if (s + 2 < 32) {
                    const int s2 = s + 2;
                    uint32_t addr = cbB + (uint32_t)((half * 32 + (s2 & 1) * 16) * 528
                                                     + ((s2 >> 1) * 16) * 2);
                    asm volatile("ldmatrix.sync.aligned.m8n8.x4.shared.b16 {%0,%1,%2,%3}, [%4];"
                                 : "=r"(bb[s & 1][0]), "=r"(bb[s & 1][1]),
                                   "=r"(bb[s & 1][2]), "=r"(bb[s & 1][3])
                                 : "r"(addr));
                }
            }

            // epilogue: score+64 > 0 -> raw float bits are the sort key
            int kbase = ch * CHUNK + half * 32 + (lane & 3) * 2;
#pragma unroll
            for (int nt = 0; nt < 4; nt++) {
#pragma unroll
                for (int e = 0; e < 4; e++) {
                    int k = kbase + nt * 8 + (e & 1);
                    float sc = __fmaf_rn(-2.0f, acc[nt][e], cn_sm[k]);
                    unsigned long long u;
                    asm("mov.b64 %0, {%1, %2};"
                        : "=l"(u) : "r"((uint32_t)k), "r"(__float_as_uint(sc)));
                    insert4(top[e >> 1], u);
                }
            }
        }

        // stage chunk ch+2 into the slot consumed at iter ch-1 (safe: sync above)
        if (ch + 2 < NCHUNK) {
            int ns = slot + 2; if (ns >= RING) ns -= RING;
            stage_c(smb + (uint32_t)(SM_RING + ns * SLOTSZ), (ch + 2) * CHUNK, tid);
        }
        asm volatile("cp.async.commit_group;" ::: "memory");  // one group per iter
        slot = (slot + 1 == RING) ? 0 : slot + 1;
    }

    // merge top-4 across the 4 lanes sharing each row, write candidates
#pragma unroll
    for (int h = 0; h < 2; h++) {
        unsigned long long v0 = top[h][0], v1 = top[h][1], v2 = top[h][2], v3 = top[h][3];
#pragma unroll
        for (int m = 1; m <= 2; m <<= 1) {
            unsigned long long o0 = __shfl_xor_sync(0xFFFFFFFFu, v0, m);
            unsigned long long o1 = __shfl_xor_sync(0xFFFFFFFFu, v1, m);
            unsigned long long o2 = __shfl_xor_sync(0xFFFFFFFFu, v2, m);
            unsigned long long o3 = __shfl_xor_sync(0xFFFFFFFFu, v3, m);
            unsigned long long s0 = v0 < o3 ? v0 : o3;
            unsigned long long s1 = v1 < o2 ? v1 : o2;
            unsigned long long s2 = v2 < o1 ? v2 : o1;
            unsigned long long s3 = v3 < o0 ? v3 : o0;
            unsigned long long a0 = s0 < s2 ? s0 : s2, a2 = s0 < s2 ? s2 : s0;
            unsigned long long a1 = s1 < s3 ? s1 : s3, a3 = s1 < s3 ? s3 : s1;
            v0 = a0 < a1 ? a0 : a1; v1 = a0 < a1 ? a1 : a0;
            v2 = a2 < a3 ? a2 : a3; v3 = a2 < a3 ? a3 : a2;
        }
        if ((lane & 3) == 0) {
            int row = rowBase + w * 16 + (lane >> 2) + h * 8;
            uint4 st;
            st.x = (uint32_t)v0; st.y = (uint32_t)v1;
            st.z = (uint32_t)v2; st.w = (uint32_t)v3;
            *(uint4*)&g_cand[row * 4] = st;
        }
    }
}

// ---------------------------------------------------------------------------
// K3: fused exact rescore + gather + loss + hist + (last CTA) EMA counts.
// warp = row; lane = (cand c = lane>>3, seg s = lane&7); element float4 q*8+s.
// ---------------------------------------------------------------------------
__global__ void __launch_bounds__(256, 3) rescore_gather_kernel(const float* __restrict__ x,
                                                                const float* __restrict__ cb,
                                                                const float* __restrict__ cc,
                                                                float* __restrict__ outq,
                                                                float* __restrict__ outl,
                                                                float* __restrict__ outnn,
                                                                float* __restrict__ outcnt) {
    int row  = (blockIdx.x * blockDim.x + threadIdx.x) >> 5;
    int lane = threadIdx.x & 31;
    int c = lane >> 3, s = lane & 7;

    unsigned int cand = g_cand[row * 4 + c];
    const float4* c4 = (const float4*)(cb + (size_t)cand * D);
    const float4* x4 = (const float4*)(x + (size_t)row * D);

    float d = 0.0f;
#pragma unroll
    for (int q = 0; q < 8; q++) {
        float4 cq = c4[q * 8 + s];
        float4 xq = x4[q * 8 + s];
        d = __fmaf_rn(xq.x, cq.x, d);
        d = __fmaf_rn(xq.y, cq.y, d);
        d = __fmaf_rn(xq.z, cq.z, d);
        d = __fmaf_rn(xq.w, cq.w, d);
    }
    d = __fadd_rn(d, __shfl_xor_sync(0xFFFFFFFFu, d, 1));
    d = __fadd_rn(d, __shfl_xor_sync(0xFFFFFFFFu, d, 2));
    d = __fadd_rn(d, __shfl_xor_sync(0xFFFFFFFFu, d, 4));

    float sc = __fadd_rn(__fmaf_rn(-2.0f, d, g_srow[row]), g_cnorm[cand]);
    uint32_t bb  = __float_as_uint(sc);
    uint32_t key = (bb & 0x80000000u) ? ~bb : (bb | 0x80000000u);
    unsigned long long best = ((unsigned long long)key << 32) | cand;

    unsigned long long o;
    o = __shfl_xor_sync(0xFFFFFFFFu, best, 8);  best = o < best ? o : best;
    o = __shfl_xor_sync(0xFFFFFFFFu, best, 16); best = o < best ? o : best;
    unsigned int wc = (unsigned int)best;

    if (lane == 0) {
        atomicAdd(&g_hist[wc], 1);
        outnn[row] = (float)wc;
    }

    if (cand == wc) {   // exactly one group (candidates are distinct)
        float4* qr = (float4*)(outq + (size_t)row * D);
        float4* lr = (float4*)(outl + (size_t)row * D);
#pragma unroll
        for (int q = 0; q < 8; q++) {
            float4 cq = c4[q * 8 + s];   // L1 hit
            float4 xq = x4[q * 8 + s];   // L1 hit
            qr[q * 8 + s] = cq;
            float4 L;
            L.x = 1.25f * (cq.x - xq.x) * (cq.x - xq.x);
            L.y = 1.25f * (cq.y - xq.y) * (cq.y - xq.y);
            L.z = 1.25f * (cq.z - xq.z) * (cq.z - xq.z);
            L.w = 1.25f * (cq.w - xq.w) * (cq.w - xq.w);
            lr[q * 8 + s] = L;
        }
    }

    // last-CTA-done: EMA counts (removes a separate launch)
    __shared__ int is_last;
    __syncthreads();
    if (threadIdx.x == 0) {
        __threadfence();
        is_last = (atomicAdd(&g_done, 1) == (int)gridDim.x - 1);
    }
    __syncthreads();
    if (is_last) {
#pragma unroll
        for (int k0 = 0; k0 < NC / 256; k0++) {
            int k = k0 * 256 + threadIdx.x;
            outcnt[k] = 0.99f * cc[k] + 0.01f * (float)g_hist[k];
        }
        __syncthreads();
        if (threadIdx.x == 0) g_done = 0;   // reset for next graph replay
    }
}

// ---------------------------------------------------------------------------
extern "C" void kernel_launch(void* const* d_in, const int* in_sizes, int n_in,
                              void* d_out, int out_size) {
    const float* x  = (const float*)d_in[0];
    const float* cb = (const float*)d_in[1];
    const float* cc = (const float*)d_in[2];
    float* out = (float*)d_out;

    cudaFuncSetAttribute(approx_kernel,
                         cudaFuncAttributeMaxDynamicSharedMemorySize, SM_TOTAL);

    init_kernel<<<384, 256>>>(x, cb, out + OFF_CB);
    approx_kernel<<<NROWS / BM, 256, SM_TOTAL>>>(x);
    rescore_gather_kernel<<<NROWS * 32 / 256, 256>>>(x, cb, cc,
                                                     out + OFF_Q, out + OFF_L,
                                                     out + OFF_NN, out + OFF_CNT);
}

// round 15
// speedup vs baseline: 1.0413x; 1.0329x over previous
#include <cuda_runtime.h>
#include <cuda_bf16.h>
#include <cstdint>

#define NC     2048
#define D      256
#define NROWS  32768
#define BM     128          // rows per CTA in approx kernel
#define CHUNK  64           // centroids per chunk
#define NCHUNK (NC / CHUNK) // 32
#define RING   3
#define SLOTSZ (CHUNK * 528)   // 33792 B per ring slot

// Output layout (float32):
#define OFF_Q    0
#define OFF_L    8388608
#define OFF_NN   16777216
#define OFF_CB   16809984
#define OFF_CNT  17334272

// SMEM map (bytes): ring (X staged here transiently) then cn.
#define SM_RING  0
#define SM_CN    (RING * SLOTSZ)          // 101376
#define SM_TOTAL (SM_CN + NC * 4)         // 109568 -> 2 CTAs/SM

// scratch (allocation-free)
__device__ float          g_cnorm[NC];
__device__ float          g_srow[NROWS];
__device__ __nv_bfloat16  g_cb[NC * D];
__device__ unsigned int   g_cand[NROWS * 4];
__device__ int            g_hist[NC];
__device__ int            g_done;          // zero-init; reset by last rescore CTA

__device__ __forceinline__ uint32_t smem_u32(const void* p) {
    uint32_t a;
    asm("{ .reg .u64 t; cvta.to.shared.u64 t, %1; cvt.u32.u64 %0, t; }" : "=r"(a) : "l"(p));
    return a;
}

__device__ __forceinline__ void insert4(unsigned long long* t, unsigned long long u) {
    if (u < t[3]) {
        if (u < t[2]) {
            t[3] = t[2];
            if (u < t[1]) {
                t[2] = t[1];
                if (u < t[0]) { t[1] = t[0]; t[0] = u; } else t[1] = u;
            } else t[2] = u;
        } else t[3] = u;
    }
}

// sequential-order ||row||^2 using packed f32x2 multiplies.
// mul.rn.f32x2 produces fl(lo^2), fl(hi^2) -- bit-identical to __fmul_rn per
// element -- and the fadd chain order q=0..255 is unchanged. 25% fewer instrs.
__device__ __forceinline__ float row_norm_seq(const float* row) {
    float s = 0.0f;
    const uint4* p = (const uint4*)row;
#pragma unroll
    for (int i = 0; i < 64; i++) {
        uint4 q = p[i];
        unsigned long long a, b, aa, bb;
        asm("mov.b64 %0, {%1, %2};" : "=l"(a) : "r"(q.x), "r"(q.y));
        asm("mov.b64 %0, {%1, %2};" : "=l"(b) : "r"(q.z), "r"(q.w));
        asm("mul.rn.f32x2 %0, %1, %1;" : "=l"(aa) : "l"(a));
        asm("mul.rn.f32x2 %0, %1, %1;" : "=l"(bb) : "l"(b));
        uint32_t l0, h0, l1, h1;
        asm("mov.b64 {%0, %1}, %2;" : "=r"(l0), "=r"(h0) : "l"(aa));
        asm("mov.b64 {%0, %1}, %2;" : "=r"(l1), "=r"(h1) : "l"(bb));
        s = __fadd_rn(s, __uint_as_float(l0));
        s = __fadd_rn(s, __uint_as_float(h0));
        s = __fadd_rn(s, __uint_as_float(l1));
        s = __fadd_rn(s, __uint_as_float(h1));
    }
    return s;
}

// ---------------------------------------------------------------------------
// K0: init (codebook side only; srow moved to approx backfill blocks).
// grid 256: cnorm + codebook copy + bf16 codebook + hist init.
// ---------------------------------------------------------------------------
__global__ void __launch_bounds__(256) init_kernel(const float* __restrict__ cb,
                                                   float* __restrict__ outcb) {
    int gid = blockIdx.x * 256 + threadIdx.x;   // 0..65535
    if (gid < NC) g_hist[gid] = 0;

    int wid  = gid >> 5;
    int lane = gid & 31;
    const float* row  = cb    + (size_t)wid * D;
    float*       orow = outcb + (size_t)wid * D;
#pragma unroll
    for (int j = 0; j < 8; j++) orow[lane + 32 * j] = row[lane + 32 * j];

    if (gid < NC)
        g_cnorm[gid] = row_norm_seq(cb + (size_t)gid * D);

    // bf16 codebook: 8 floats/thread
    {
        const float4* src = (const float4*)cb;
        float4 v0 = src[gid * 2], v1 = src[gid * 2 + 1];
        __nv_bfloat16 bb[8];
        bb[0] = __float2bfloat16(v0.x); bb[1] = __float2bfloat16(v0.y);
        bb[2] = __float2bfloat16(v0.z); bb[3] = __float2bfloat16(v0.w);
        bb[4] = __float2bfloat16(v1.x); bb[5] = __float2bfloat16(v1.y);
        bb[6] = __float2bfloat16(v1.z); bb[7] = __float2bfloat16(v1.w);
        ((uint4*)g_cb)[gid] = *(uint4*)bb;
    }
}

// cp.async one 64-centroid bf16 chunk into a ring slot (row stride 528B)
__device__ __forceinline__ void stage_c(uint32_t dst, int cbase, int tid) {
    const char* src = (const char*)(g_cb + (size_t)cbase * D);
#pragma unroll
    for (int i = 0; i < 8; i++) {
        int idx = tid + i * 256;              // 0..2047
        int r = idx >> 5, kp = (idx & 31) * 16;
        uint32_t d = dst + (uint32_t)(r * 528 + kp);
        const char* s = src + r * 512 + kp;
        asm volatile("cp.async.ca.shared.global [%0], [%1], 16;" :: "r"(d), "l"(s));
    }
}

// ---------------------------------------------------------------------------
// K2: HMMA bf16 approx GEMM + fused per-row top-4. 256 thr, 2 CTAs/SM.
// Blocks [0,256): 128 rows x 2048 centroids (warp w owns rows [w*16,w*16+16)).
// Blocks [256,384): srow backfill -- per-row sequential ||x||^2 (needed only
// by rescore), scheduled into the under-filled wave slots / gemm tail.
// ---------------------------------------------------------------------------
__global__ void __launch_bounds__(256, 2) approx_kernel(const float* __restrict__ x) {
    extern __shared__ char sm[];
    const int tid = threadIdx.x;

    if (blockIdx.x >= 256) {   // srow backfill block
        int r = (blockIdx.x - 256) * 256 + tid;
        g_srow[r] = row_norm_seq(x + (size_t)r * D);
        return;
    }

    float* cn_sm = (float*)(sm + SM_CN);
    const int lane = tid & 31;
    const int w    = tid >> 5;
    const int rowBase = blockIdx.x * BM;
    const uint32_t smb = smem_u32(sm);

    for (int i = tid; i < NC; i += 256) cn_sm[i] = g_cnorm[i] + 64.0f;

    // stage X (fp32 -> bf16) into ring region transiently (128 * 528 B)
#pragma unroll
    for (int i = 0; i < 16; i++) {
        int idx = tid + i * 256;
        int r = idx >> 5, kp = (idx & 31) * 8;
        const float4* src = (const float4*)(x + (size_t)(rowBase + r) * D + kp);
        float4 v0 = src[0], v1 = src[1];
        __nv_bfloat16 bb[8];
        bb[0] = __float2bfloat16(v0.x); bb[1] = __float2bfloat16(v0.y);
        bb[2] = __float2bfloat16(v0.z); bb[3] = __float2bfloat16(v0.w);
        bb[4] = __float2bfloat16(v1.x); bb[5] = __float2bfloat16(v1.y);
        bb[6] = __float2bfloat16(v1.z); bb[7] = __float2bfloat16(v1.w);
        *(uint4*)(sm + r * 528 + kp * 2) = *(uint4*)bb;
    }
    __syncthreads();

    // A fragments held in regs: 16 k-blocks (m16k16 each)
    uint32_t a[16][4];
#pragma unroll
    for (int kb = 0; kb < 16; kb++) {
        uint32_t addr = smb + (uint32_t)((w * 16 + (lane & 15)) * 528
                                         + (kb * 16 + (lane >> 4) * 8) * 2);
        asm volatile("ldmatrix.sync.aligned.m8n8.x4.shared.b16 {%0,%1,%2,%3}, [%4];"
                     : "=r"(a[kb][0]), "=r"(a[kb][1]), "=r"(a[kb][2]), "=r"(a[kb][3])
                     : "r"(addr));
    }
    __syncthreads();   // X region now dead; becomes the C ring

    // prologue: stage chunks 0 and 1 into slots 0 and 1
    stage_c(smb + SM_RING + 0 * SLOTSZ, 0 * CHUNK, tid);
    asm volatile("cp.async.commit_group;" ::: "memory");
    stage_c(smb + SM_RING + 1 * SLOTSZ, 1 * CHUNK, tid);
    asm volatile("cp.async.commit_group;" ::: "memory");

    unsigned long long top[2][4];
#pragma unroll
    for (int h = 0; h < 2; h++)
#pragma unroll
        for (int j = 0; j < 4; j++) top[h][j] = 0xFFFFFFFFFFFFFFFFULL;

    const uint32_t bRowOff = (uint32_t)(((lane & 7) + (lane >> 4) * 8) * 528
                                        + ((lane >> 3) & 1) * 16);

    int slot = 0;
    for (int ch = 0; ch < NCHUNK; ch++) {
        asm volatile("cp.async.wait_group 1;" ::: "memory");
        __syncthreads();   // slot `slot` (chunk ch) visible to all warps

        const uint32_t cbB = smb + (uint32_t)(SM_RING + slot * SLOTSZ) + bRowOff;

#pragma unroll
        for (int half = 0; half < 2; half++) {
            float acc[4][4];
#pragma unroll
            for (int nt = 0; nt < 4; nt++)
#pragma unroll
                for (int e = 0; e < 4; e++) acc[nt][e] = 0.0f;

            // flattened steps s = kb*2 + np; 2-slot B-frag ring, prefetch +2
            uint32_t bb[2][4];
#pragma unroll
            for (int p = 0; p < 2; p++) {
                uint32_t addr = cbB + (uint32_t)((half * 32 + p * 16) * 528);
                asm volatile("ldmatrix.sync.aligned.m8n8.x4.shared.b16 {%0,%1,%2,%3}, [%4];"
                             : "=r"(bb[p][0]), "=r"(bb[p][1]), "=r"(bb[p][2]), "=r"(bb[p][3])
                             : "r"(addr));
            }
#pragma unroll
            for (int s = 0; s < 32; s++) {
                const int kb = s >> 1, np = s & 1;
                asm volatile("mma.sync.aligned.m16n8k16.row.col.f32.bf16.bf16.f32 "
                             "{%0,%1,%2,%3}, {%4,%5,%6,%7}, {%8,%9}, {%0,%1,%2,%3};"
                             : "+f"(acc[np*2][0]), "+f"(acc[np*2][1]),
                               "+f"(acc[np*2][2]), "+f"(acc[np*2][3])
                             : "r"(a[kb][0]), "r"(a[kb][1]), "r"(a[kb][2]), "r"(a[kb][3]),
                               "r"(bb[s & 1][0]), "r"(bb[s & 1][1]));
                asm volatile("mma.sync.aligned.m16n8k16.row.col.f32.bf16.bf16.f32 "
                             "{%0,%1,%2,%3}, {%4,%5,%6,%7}, {%8,%9}, {%0,%1,%2,%3};"
                             : "+f"(acc[np*2+1][0]), "+f"(acc[np*2+1][1]),
                               "+f"(acc[np*2+1][2]), "+f"(acc[np*2+1][3])
                             : "r"(a[kb][0]), "r"(a[kb][1]), "r"(a[kb][2]), "r"(a[kb][3]),
                               "r"(bb[s & 1][2]), "r"(bb[s & 1][3]));
                if (s + 2 < 32) {
                    const int s2 = s + 2;
                    uint32_t addr = cbB + (uint32_t)((half * 32 + (s2 & 1) * 16) * 528
                                                     + ((s2 >> 1) * 16) * 2);
                    asm volatile("ldmatrix.sync.aligned.m8n8.x4.shared.b16 {%0,%1,%2,%3}, [%4];"
                                 : "=r"(bb[s & 1][0]), "=r"(bb[s & 1][1]),
                                   "=r"(bb[s & 1][2]), "=r"(bb[s & 1][3])
                                 : "r"(addr));
                }
            }

            // epilogue: score+64 > 0 -> raw float bits are the sort key
            int kbase = ch * CHUNK + half * 32 + (lane & 3) * 2;
#pragma unroll
            for (int nt = 0; nt < 4; nt++) {
#pragma unroll
                for (int e = 0; e < 4; e++) {
                    int k = kbase + nt * 8 + (e & 1);
                    float sc = __fmaf_rn(-2.0f, acc[nt][e], cn_sm[k]);
                    unsigned long long u;
                    asm("mov.b64 %0, {%1, %2};"
                        : "=l"(u) : "r"((uint32_t)k), "r"(__float_as_uint(sc)));
                    insert4(top[e >> 1], u);
                }
            }
        }

        // stage chunk ch+2 into the slot consumed at iter ch-1 (safe: sync above)
        if (ch + 2 < NCHUNK) {
            int ns = slot + 2; if (ns >= RING) ns -= RING;
            stage_c(smb + (uint32_t)(SM_RING + ns * SLOTSZ), (ch + 2) * CHUNK, tid);
        }
        asm volatile("cp.async.commit_group;" ::: "memory");  // one group per iter
        slot = (slot + 1 == RING) ? 0 : slot + 1;
    }

    // merge top-4 across the 4 lanes sharing each row, write candidates
#pragma unroll
    for (int h = 0; h < 2; h++) {
        unsigned long long v0 = top[h][0], v1 = top[h][1], v2 = top[h][2], v3 = top[h][3];
#pragma unroll
        for (int m = 1; m <= 2; m <<= 1) {
            unsigned long long o0 = __shfl_xor_sync(0xFFFFFFFFu, v0, m);
            unsigned long long o1 = __shfl_xor_sync(0xFFFFFFFFu, v1, m);
            unsigned long long o2 = __shfl_xor_sync(0xFFFFFFFFu, v2, m);
            unsigned long long o3 = __shfl_xor_sync(0xFFFFFFFFu, v3, m);
            unsigned long long s0 = v0 < o3 ? v0 : o3;
            unsigned long long s1 = v1 < o2 ? v1 : o2;
            unsigned long long s2 = v2 < o1 ? v2 : o1;
            unsigned long long s3 = v3 < o0 ? v3 : o0;
            unsigned long long a0 = s0 < s2 ? s0 : s2, a2 = s0 < s2 ? s2 : s0;
            unsigned long long a1 = s1 < s3 ? s1 : s3, a3 = s1 < s3 ? s3 : s1;
            v0 = a0 < a1 ? a0 : a1; v1 = a0 < a1 ? a1 : a0;
            v2 = a2 < a3 ? a2 : a3; v3 = a2 < a3 ? a3 : a2;
        }
        if ((lane & 3) == 0) {
            int row = rowBase + w * 16 + (lane >> 2) + h * 8;
            uint4 st;
            st.x = (uint32_t)v0; st.y = (uint32_t)v1;
            st.z = (uint32_t)v2; st.w = (uint32_t)v3;
            *(uint4*)&g_cand[row * 4] = st;
        }
    }
}

// ---------------------------------------------------------------------------
// K3: fused exact rescore + gather + loss + hist + (last CTA) EMA counts.
// warp = row; lane = (cand c = lane>>3, seg s = lane&7); element float4 q*8+s.
// ---------------------------------------------------------------------------
__global__ void __launch_bounds__(256, 3) rescore_gather_kernel(const float* __restrict__ x,
                                                                const float* __restrict__ cb,
                                                                const float* __restrict__ cc,
                                                                float* __restrict__ outq,
                                                                float* __restrict__ outl,
                                                                float* __restrict__ outnn,
                                                                float* __restrict__ outcnt) {
    int row  = (blockIdx.x * blockDim.x + threadIdx.x) >> 5;
    int lane = threadIdx.x & 31;
    int c = lane >> 3, s = lane & 7;

    unsigned int cand = g_cand[row * 4 + c];
    const float4* c4 = (const float4*)(cb + (size_t)cand * D);
    const float4* x4 = (const float4*)(x + (size_t)row * D);

    float d = 0.0f;
#pragma unroll
    for (int q = 0; q < 8; q++) {
        float4 cq = c4[q * 8 + s];
        float4 xq = x4[q * 8 + s];
        d = __fmaf_rn(xq.x, cq.x, d);
        d = __fmaf_rn(xq.y, cq.y, d);
        d = __fmaf_rn(xq.z, cq.z, d);
        d = __fmaf_rn(xq.w, cq.w, d);
    }
    d = __fadd_rn(d, __shfl_xor_sync(0xFFFFFFFFu, d, 1));
    d = __fadd_rn(d, __shfl_xor_sync(0xFFFFFFFFu, d, 2));
    d = __fadd_rn(d, __shfl_xor_sync(0xFFFFFFFFu, d, 4));

    float sc = __fadd_rn(__fmaf_rn(-2.0f, d, g_srow[row]), g_cnorm[cand]);
    uint32_t bb  = __float_as_uint(sc);
    uint32_t key = (bb & 0x80000000u) ? ~bb : (bb | 0x80000000u);
    unsigned long long best = ((unsigned long long)key << 32) | cand;

    unsigned long long o;
    o = __shfl_xor_sync(0xFFFFFFFFu, best, 8);  best = o < best ? o : best;
    o = __shfl_xor_sync(0xFFFFFFFFu, best, 16); best = o < best ? o : best;
    unsigned int wc = (unsigned int)best;

    if (lane == 0) {
        atomicAdd(&g_hist[wc], 1);
        outnn[row] = (float)wc;
    }

    if (cand == wc) {   // exactly one group (candidates are distinct)
        float4* qr = (float4*)(outq + (size_t)row * D);
        float4* lr = (float4*)(outl + (size_t)row * D);
#pragma unroll
        for (int q = 0; q < 8; q++) {
            float4 cq = c4[q * 8 + s];   // L1 hit
            float4 xq = x4[q * 8 + s];   // L1 hit
            qr[q * 8 + s] = cq;
            float4 L;
            L.x = 1.25f * (cq.x - xq.x) * (cq.x - xq.x);
            L.y = 1.25f * (cq.y - xq.y) * (cq.y - xq.y);
            L.z = 1.25f * (cq.z - xq.z) * (cq.z - xq.z);
            L.w = 1.25f * (cq.w - xq.w) * (cq.w - xq.w);
            lr[q * 8 + s] = L;
        }
    }

    // last-CTA-done: EMA counts (removes a separate launch)
    __shared__ int is_last;
    __syncthreads();
    if (threadIdx.x == 0) {
        __threadfence();
        is_last = (atomicAdd(&g_done, 1) == (int)gridDim.x - 1);
    }
    __syncthreads();
    if (is_last) {
#pragma unroll
        for (int k0 = 0; k0 < NC / 256; k0++) {
            int k = k0 * 256 + threadIdx.x;
            outcnt[k] = 0.99f * cc[k] + 0.01f * (float)g_hist[k];
        }
        __syncthreads();
        if (threadIdx.x == 0) g_done = 0;   // reset for next graph replay
    }
}

// ---------------------------------------------------------------------------
extern "C" void kernel_launch(void* const* d_in, const int* in_sizes, int n_in,
                              void* d_out, int out_size) {
    const float* x  = (const float*)d_in[0];
    const float* cb = (const float*)d_in[1];
    const float* cc = (const float*)d_in[2];
    float* out = (float*)d_out;

    cudaFuncSetAttribute(approx_kernel,
                         cudaFuncAttributeMaxDynamicSharedMemorySize, SM_TOTAL);

    init_kernel<<<256, 256>>>(cb, out + OFF_CB);
    approx_kernel<<<NROWS / BM + 128, 256, SM_TOTAL>>>(x);
    rescore_gather_kernel<<<NROWS * 32 / 256, 256>>>(x, cb, cc,
                                                     out + OFF_Q, out + OFF_L,
                                                     out + OFF_NN, out + OFF_CNT);
}